// round 13
// baseline (speedup 1.0000x reference)
#include <cuda_runtime.h>
#include <math.h>

// x: [16, 4, 2048, 257] fp32 -> BM=64 series-groups, T=2048, F=257
#define BM_      64
#define T_       2048
#define F_       257
#define CLEN     32                 // frames per chunk
#define NCH      (T_ / CLEN)        // 64 chunks per series
#define GRID_    (BM_ * NCH)        // 4096 = 2^12 blocks per launch
#define NTHREADS 288                // 9 warps; threads [0,257) active
#define EPS_     1e-6f

// Chain scratch. g_mend: prefix-EMA tails (plain data, guarded by flag).
// g_flag: per-(bm,chunk) epoch tag; tag for this launch = (ticket>>12)+1,
// strictly increasing across (serialized) launches -> reset-free.
__device__ float        g_mend[BM_ * NCH * F_];
__device__ unsigned int g_flag[BM_ * NCH];
__device__ unsigned int g_ticket;

__device__ __forceinline__ float ld_relaxed_gpu(const float* p) {
    float v; asm volatile("ld.relaxed.gpu.f32 %0, [%1];" : "=f"(v) : "l"(p)); return v;
}
__device__ __forceinline__ void st_relaxed_gpu(float* p, float v) {
    asm volatile("st.relaxed.gpu.f32 [%0], %1;" :: "l"(p), "f"(v));
}
__device__ __forceinline__ unsigned int ld_acquire_gpu(const unsigned int* p) {
    unsigned int v; asm volatile("ld.acquire.gpu.u32 %0, [%1];" : "=r"(v) : "l"(p)); return v;
}
__device__ __forceinline__ void st_release_gpu(unsigned int* p, unsigned int v) {
    asm volatile("st.release.gpu.u32 [%0], %1;" :: "l"(p), "r"(v));
}
__device__ __forceinline__ float lg2f(float v) { float r; asm("lg2.approx.f32 %0, %1;" : "=f"(r) : "f"(v)); return r; }
__device__ __forceinline__ float ex2f(float v) { float r; asm("ex2.approx.f32 %0, %1;" : "=f"(r) : "f"(v)); return r; }
__device__ __forceinline__ float rsqf(float v) { float r; asm("rsqrt.approx.f32 %0, %1;" : "=f"(r) : "f"(v)); return r; }

__global__ __launch_bounds__(NTHREADS, 5)
void pcen_kernel(const float* __restrict__ x,
                 const float* __restrict__ s_p,
                 const float* __restrict__ alpha_p,
                 const float* __restrict__ delta_p,
                 const float* __restrict__ r_p,
                 float* __restrict__ out) {
    // Per-frame local-EMA stash; each thread touches only its own f column.
    __shared__ float sml[CLEN][F_];
    __shared__ unsigned int s_vb;

    // Ticket-order virtualization: waiter's predecessor always holds a smaller
    // ticket -> resident or finished -> deadlock-free across waves.
    if (threadIdx.x == 0) s_vb = atomicAdd(&g_ticket, 1u);
    __syncthreads();
    const unsigned int tk  = s_vb;
    const int vb  = (int)(tk & (GRID_ - 1));
    const unsigned int tag = (tk >> 12) + 1u;   // this launch's epoch tag (>=1)
    const int bm = vb & (BM_ - 1);              // fast-varying: all chains advance per wave
    const int c  = vb >> 6;                     // chunk index along T

    const int f = threadIdx.x;
    if (f >= F_) return;

    const float s     = s_p[0];
    const float alpha = alpha_p[0];
    const float delta = delta_p[0];
    const float r     = r_p[0];
    const float oms   = 1.0f - s;
    const float inv_s = 1.0f / s;

    const size_t base = ((size_t)bm * T_ + (size_t)c * CLEN) * F_ + f;
    const float* xp = x + base;

    // ---- Phase A: read x ONCE; zero-init local EMA; stash per-frame m_loc ----
    float m;
    {
        const float x0 = __ldg(xp);
        m = (c == 0) ? x0 : (s * x0);           // chunk 0: exact M_0 = x_0
        sml[0][f] = m;
#pragma unroll
        for (int i = 1; i < CLEN; i++) {
            m = fmaf(oms, m, s * __ldg(xp + (size_t)i * F_));
            sml[i][f] = m;
        }
    }

    // ---- Phase B: chain handshake (one flag poll per block) ----
    const size_t slot = (size_t)bm * NCH + (size_t)c;
    float m_in = 0.0f;
    if (c > 0) {
        if (f == 0) {                           // single poller; others park at BAR
            const unsigned int* fl = &g_flag[slot - 1];
            while (ld_acquire_gpu(fl) != tag) __nanosleep(32);
        }
        __syncthreads();                        // broadcasts the acquire cta-wide
        m_in = ld_relaxed_gpu(&g_mend[(slot - 1) * F_ + f]);
        float D = oms;                          // (1-s)^32 by repeated squaring
#pragma unroll
        for (int k = 0; k < 5; k++) D *= D;
        m = fmaf(D, m_in, m);                   // full prefix tail for this chunk
    }
    st_relaxed_gpu(&g_mend[slot * F_ + f], m);
    __syncthreads();                            // all 257 tails stored
    if (f == 0) {
        asm volatile("fence.acq_rel.gpu;" ::: "memory");
        st_release_gpu(&g_flag[slot], tag);     // publish
    }

    // ---- Phase C: dependence-free reconstruction + PCEN (no global reads) ----
    // mm_i = m_loc_i + oms^(i+1)*m_in ;  x_i = (m_loc_i - oms*m_loc_{i-1})/s
    const bool  half = (r == 0.5f);
    const float dr   = half ? sqrtf(delta) : ex2f(r * lg2f(delta));

    float* op = out + base;
    float eg   = oms * m_in;                    // oms^(i+1) * m_in
    float prev = 0.0f;
#pragma unroll 8
    for (int i = 0; i < CLEN; i++) {
        const float ml = sml[i][f];
        const float mm = ml + eg;               // exact full-state M (m_in=0 for c==0)
        float xv;
        if (i == 0) xv = (c == 0) ? ml : ml * inv_s;
        else        xv = (ml - oms * prev) * inv_s;
        prev = ml;
        eg *= oms;
        const float pw = ex2f(-alpha * lg2f(mm + EPS_));   // (M+eps)^(-alpha)
        const float u  = fmaf(xv, pw, delta);
        const float o  = half ? fmaf(u, rsqf(u), -dr)      // sqrt(u) = u*rsqrt(u)
                              : (ex2f(r * lg2f(u)) - dr);
        op[(size_t)i * F_] = o;
    }
}

extern "C" void kernel_launch(void* const* d_in, const int* in_sizes, int n_in,
                              void* d_out, int out_size) {
    const float* x     = (const float*)d_in[0];
    const float* s     = (const float*)d_in[1];
    const float* alpha = (const float*)d_in[2];
    const float* delta = (const float*)d_in[3];
    const float* r     = (const float*)d_in[4];
    float* out = (float*)d_out;

    (void)in_sizes; (void)n_in; (void)out_size;

    pcen_kernel<<<GRID_, NTHREADS>>>(x, s, alpha, delta, r, out);
}

// round 14
// speedup vs baseline: 1.8283x; 1.8283x over previous
#include <cuda_runtime.h>
#include <math.h>

// x: [16, 4, 2048, 257] fp32 -> BM=64 series-groups, T=2048, F=257
#define BM_      64
#define T_       2048
#define F_       257
#define CLEN     32                 // frames per chunk
#define NCH      (T_ / CLEN)        // 64 chunks per series
#define GRID_    (BM_ * NCH)        // 4096 = 2^12 blocks per launch
#define NTHREADS 288                // 9 warps; threads [0,257) active
#define EPS_     1e-6f

// Published prefix-EMA tail per (bm, chunk, f). NO reset kernel: values are
// epoch-parity encoded (even epoch: -(m+1) <= -1, odd epoch: m >= 0). Launches
// serialize, so stale entries are always opposite-parity -> rejected; initial
// zero-init memory is rejected by the even-parity predicate (needs v <= -1).
__device__ float        g_mend[BM_ * NCH * F_];
__device__ unsigned int g_ticket;   // monotonically increasing across launches

__device__ __forceinline__ float ld_relaxed_gpu(const float* p) {
    float v; asm volatile("ld.relaxed.gpu.f32 %0, [%1];" : "=f"(v) : "l"(p)); return v;
}
__device__ __forceinline__ void st_relaxed_gpu(float* p, float v) {
    asm volatile("st.relaxed.gpu.f32 [%0], %1;" :: "l"(p), "f"(v));
}
__device__ __forceinline__ float lg2f(float v) { float r; asm("lg2.approx.f32 %0, %1;" : "=f"(r) : "f"(v)); return r; }
__device__ __forceinline__ float ex2f(float v) { float r; asm("ex2.approx.f32 %0, %1;" : "=f"(r) : "f"(v)); return r; }
__device__ __forceinline__ float rsqf(float v) { float r; asm("rsqrt.approx.f32 %0, %1;" : "=f"(r) : "f"(v)); return r; }

__global__ __launch_bounds__(NTHREADS, 5)
void pcen_kernel(const float* __restrict__ x,
                 const float* __restrict__ s_p,
                 const float* __restrict__ alpha_p,
                 const float* __restrict__ delta_p,
                 const float* __restrict__ r_p,
                 float* __restrict__ out) {
    // Per-frame local-EMA stash; each thread touches only its own f column
    // -> no __syncthreads needed for it. 32.9 KB static smem.
    __shared__ float sml[CLEN][F_];
    __shared__ unsigned int s_vb;

    // Ticket-order virtualization: a waiter's predecessor always holds a
    // smaller ticket -> resident or finished -> deadlock-free across waves.
    if (threadIdx.x == 0) s_vb = atomicAdd(&g_ticket, 1u);
    __syncthreads();
    const unsigned int tk = s_vb;
    const int vb     = (int)(tk & (GRID_ - 1));
    const int parity = (int)((tk >> 12) & 1u);  // flips each launch (GRID_=2^12)
    const int bm = vb & (BM_ - 1);              // fast-varying: all chains advance per wave
    const int c  = vb >> 6;                     // chunk index along T

    const int f = threadIdx.x;
    if (f >= F_) return;

    const float s     = s_p[0];
    const float alpha = alpha_p[0];
    const float delta = delta_p[0];
    const float r     = r_p[0];
    const float oms   = 1.0f - s;
    const float inv_s = 1.0f / s;

    const size_t base = ((size_t)bm * T_ + (size_t)c * CLEN) * F_ + f;
    const float* xp = x + base;

    // ---- Phase A: read x ONCE; zero-init local EMA; stash per-frame m_loc ----
    float m;
    {
        const float x0 = __ldg(xp);
        m = (c == 0) ? x0 : (s * x0);           // chunk 0: exact M_0 = x_0
        sml[0][f] = m;
#pragma unroll
        for (int i = 1; i < CLEN; i++) {
            m = fmaf(oms, m, s * __ldg(xp + (size_t)i * F_));
            sml[i][f] = m;
        }
    }

    // ---- Phase B: per-f value-as-flag spin (parity encoded, fence-free) ----
    const size_t slot = (size_t)bm * NCH + (size_t)c;
    float m_in = 0.0f;
    if (c > 0) {
        const float* prev = &g_mend[(slot - 1) * F_ + f];
        float v;
        if (parity == 0) {                      // predecessor encodes -(m+1) <= -1
            do { v = ld_relaxed_gpu(prev); } while (v > -1.0f);
            m_in = -v - 1.0f;
        } else {                                // predecessor encodes m >= 0
            do { v = ld_relaxed_gpu(prev); } while (v < 0.0f);
            m_in = v;
        }
        float D = oms;                          // (1-s)^32 by repeated squaring
#pragma unroll
        for (int k = 0; k < 5; k++) D *= D;
        m = fmaf(D, m_in, m);                   // full prefix tail for this chunk
    }
    {
        const float enc = (parity == 0) ? (-(m + 1.0f)) : m;
        st_relaxed_gpu(&g_mend[slot * F_ + f], enc);   // publish ASAP
    }

    // ---- Phase C: dependence-free reconstruction + PCEN (no global reads) ----
    // mm_i = m_loc_i + oms^(i+1)*m_in ;  x_i = (m_loc_i - oms*m_loc_{i-1})/s
    const bool  half = (r == 0.5f);
    const float dr   = half ? sqrtf(delta) : ex2f(r * lg2f(delta));

    float* op = out + base;
    float eg   = oms * m_in;                    // oms^(i+1) * m_in
    float prev = 0.0f;
#pragma unroll 8
    for (int i = 0; i < CLEN; i++) {
        const float ml = sml[i][f];
        const float mm = ml + eg;               // exact full-state M (m_in=0 for c==0)
        float xv;
        if (i == 0) xv = (c == 0) ? ml : ml * inv_s;
        else        xv = (ml - oms * prev) * inv_s;
        prev = ml;
        eg *= oms;
        const float pw = ex2f(-alpha * lg2f(mm + EPS_));   // (M+eps)^(-alpha)
        const float u  = fmaf(xv, pw, delta);
        const float o  = half ? fmaf(u, rsqf(u), -dr)      // sqrt(u) = u*rsqrt(u)
                              : (ex2f(r * lg2f(u)) - dr);
        op[(size_t)i * F_] = o;
    }
}

extern "C" void kernel_launch(void* const* d_in, const int* in_sizes, int n_in,
                              void* d_out, int out_size) {
    const float* x     = (const float*)d_in[0];
    const float* s     = (const float*)d_in[1];
    const float* alpha = (const float*)d_in[2];
    const float* delta = (const float*)d_in[3];
    const float* r     = (const float*)d_in[4];
    float* out = (float*)d_out;

    (void)in_sizes; (void)n_in; (void)out_size;

    pcen_kernel<<<GRID_, NTHREADS>>>(x, s, alpha, delta, r, out);
}